// round 3
// baseline (speedup 1.0000x reference)
#include <cuda_runtime.h>
#include <cuda_bf16.h>

#define K_BONES 512

typedef unsigned long long u64;

// Per bone, 4 float4s (64 B), laid out so packed-pairs are natural:
//   [0] = (bx, by, bz, 0)
//   [1] = (R00, R01, R02, t0)   row0 of [R|t]
//   [2] = (R10, R11, R12, t1)
//   [3] = (R20, R21, R22, t2)
__device__ float4 g_bones[K_BONES * 4];

// ---------------------------------------------------------------------------
// Precompute: 6D rotation -> rotmat (Gram-Schmidt) + pack. 512 threads total.
// rotcont reshape(3,2) row-major: a1=(p0,p2,p4), a2=(p1,p3,p5).
// rotmat columns are (b1,b2,b3) => row i = (b1[i], b2[i], b3[i]).
// ---------------------------------------------------------------------------
__global__ void prep_kernel(const float* __restrict__ bone_locs,
                            const float* __restrict__ bone_transf,
                            const int* __restrict__ tidx_p) {
    int k = blockIdx.x * blockDim.x + threadIdx.x;
    if (k >= K_BONES) return;
    const float* p = bone_transf + ((long long)tidx_p[0] * K_BONES + k) * 9;

    float a1x = p[0], a2x = p[1];
    float a1y = p[2], a2y = p[3];
    float a1z = p[4], a2z = p[5];

    float n1 = sqrtf(a1x * a1x + a1y * a1y + a1z * a1z) + 1e-12f;
    float b1x = a1x / n1, b1y = a1y / n1, b1z = a1z / n1;

    float d = b1x * a2x + b1y * a2y + b1z * a2z;
    float cx = a2x - d * b1x, cy = a2y - d * b1y, cz = a2z - d * b1z;
    float n2 = sqrtf(cx * cx + cy * cy + cz * cz) + 1e-12f;
    float b2x = cx / n2, b2y = cy / n2, b2z = cz / n2;

    float b3x = b1y * b2z - b1z * b2y;
    float b3y = b1z * b2x - b1x * b2z;
    float b3z = b1x * b2y - b1y * b2x;

    g_bones[4 * k + 0] = make_float4(bone_locs[3 * k + 0], bone_locs[3 * k + 1],
                                     bone_locs[3 * k + 2], 0.0f);
    g_bones[4 * k + 1] = make_float4(b1x, b2x, b3x, p[6]);
    g_bones[4 * k + 2] = make_float4(b1y, b2y, b3y, p[7]);
    g_bones[4 * k + 3] = make_float4(b1z, b2z, b3z, p[8]);
}

// ---- packed f32x2 helpers (sm_100a) ---------------------------------------
__device__ __forceinline__ u64 pk2(float lo, float hi) {
    u64 r;
    asm("mov.b64 %0, {%1, %2};" : "=l"(r) : "f"(lo), "f"(hi));
    return r;
}
__device__ __forceinline__ void upk2(u64 v, float& lo, float& hi) {
    asm("mov.b64 {%0, %1}, %2;" : "=f"(lo), "=f"(hi) : "l"(v));
}
__device__ __forceinline__ u64 addx2(u64 a, u64 b) {
    u64 r;
    asm("add.rn.f32x2 %0, %1, %2;" : "=l"(r) : "l"(a), "l"(b));
    return r;
}
__device__ __forceinline__ u64 mulx2(u64 a, u64 b) {
    u64 r;
    asm("mul.rn.f32x2 %0, %1, %2;" : "=l"(r) : "l"(a), "l"(b));
    return r;
}
__device__ __forceinline__ u64 fmax2(u64 a, u64 b, u64 c) {
    u64 r;
    asm("fma.rn.f32x2 %0, %1, %2, %3;" : "=l"(r) : "l"(a), "l"(b), "l"(c));
    return r;
}

// ---------------------------------------------------------------------------
// Main kernel: 2 points per thread — each bone's 64 B of shared data is
// loaded ONCE (4 broadcast LDS.128) and consumed by two independent point
// computations, halving LDS traffic per point-bone (the round-2 binder).
// One-pass no-max softmax fused with the transform blend.
// ---------------------------------------------------------------------------
__global__ __launch_bounds__(256)
void skin_kernel(const float* __restrict__ xyz,
                 float* __restrict__ out, int n) {
    __shared__ ulonglong2 sb[K_BONES * 4];   // 32 KB
    {
        const ulonglong2* gb = (const ulonglong2*)g_bones;
        for (int i = threadIdx.x; i < K_BONES * 4; i += blockDim.x)
            sb[i] = gb[i];
    }
    __syncthreads();

    int base = blockIdx.x * (blockDim.x * 2);
    int i0 = base + threadIdx.x;
    int i1 = i0 + blockDim.x;
    bool v0 = i0 < n, v1 = i1 < n;

    float x0 = 0.f, y0 = 0.f, z0 = 0.f, x1 = 0.f, y1 = 0.f, z1 = 0.f;
    if (v0) { x0 = xyz[3 * i0]; y0 = xyz[3 * i0 + 1]; z0 = xyz[3 * i0 + 2]; }
    if (v1) { x1 = xyz[3 * i1]; y1 = xyz[3 * i1 + 1]; z1 = xyz[3 * i1 + 2]; }

    u64 nxy0 = pk2(-x0, -y0);
    u64 nxy1 = pk2(-x1, -y1);

    float s0 = 0.f, s1 = 0.f;
    u64 B01 = 0, B23 = 0, B45 = 0, B67 = 0, B89 = 0, BAB = 0;  // point0
    u64 C01 = 0, C23 = 0, C45 = 0, C67 = 0, C89 = 0, CAB = 0;  // point1

    const float C = -28.853900817779268f;  // -SIGMA * log2(e), SIGMA = 20

    const ulonglong2* p = sb;
    #pragma unroll 4
    for (int k = 0; k < K_BONES; k++, p += 4) {
        ulonglong2 qa = p[0];   // (bx,by) | (bz, 0)
        ulonglong2 qb = p[1];   // (R00,R01) | (R02,t0)
        ulonglong2 qc = p[2];   // (R10,R11) | (R12,t1)
        ulonglong2 qd = p[3];   // (R20,R21) | (R22,t2)
        float bz, pad;  upk2(qa.y, bz, pad);

        // ---- point 0 ----
        {
            u64 dxy = addx2(qa.x, nxy0);
            float dz = bz - z0;
            u64 dxy2 = mulx2(dxy, dxy);
            float t0, t1;  upk2(dxy2, t0, t1);
            float d2 = fmaf(dz, dz, t0) + t1;
            float dist;
            asm("sqrt.approx.f32 %0, %1;" : "=f"(dist) : "f"(d2));
            float e;
            asm("ex2.approx.f32 %0, %1;" : "=f"(e) : "f"(dist * C));
            s0 += e;
            u64 e2 = pk2(e, e);
            B01 = fmax2(e2, qb.x, B01);  B23 = fmax2(e2, qb.y, B23);
            B45 = fmax2(e2, qc.x, B45);  B67 = fmax2(e2, qc.y, B67);
            B89 = fmax2(e2, qd.x, B89);  BAB = fmax2(e2, qd.y, BAB);
        }
        // ---- point 1 ----
        {
            u64 dxy = addx2(qa.x, nxy1);
            float dz = bz - z1;
            u64 dxy2 = mulx2(dxy, dxy);
            float t0, t1;  upk2(dxy2, t0, t1);
            float d2 = fmaf(dz, dz, t0) + t1;
            float dist;
            asm("sqrt.approx.f32 %0, %1;" : "=f"(dist) : "f"(d2));
            float e;
            asm("ex2.approx.f32 %0, %1;" : "=f"(e) : "f"(dist * C));
            s1 += e;
            u64 e2 = pk2(e, e);
            C01 = fmax2(e2, qb.x, C01);  C23 = fmax2(e2, qb.y, C23);
            C45 = fmax2(e2, qc.x, C45);  C67 = fmax2(e2, qc.y, C67);
            C89 = fmax2(e2, qd.x, C89);  CAB = fmax2(e2, qd.y, CAB);
        }
    }

    if (v0) {
        float inv;
        asm("rcp.approx.f32 %0, %1;" : "=f"(inv) : "f"(s0));
        float A0, A1, A2, A3, A4, A5, A6, A7, A8, A9, A10, A11;
        upk2(B01, A0, A1);  upk2(B23, A2, A3);
        upk2(B45, A4, A5);  upk2(B67, A6, A7);
        upk2(B89, A8, A9);  upk2(BAB, A10, A11);
        out[3 * i0 + 0] = fmaf(A0, x0, fmaf(A1, y0, fmaf(A2, z0, A3))) * inv;
        out[3 * i0 + 1] = fmaf(A4, x0, fmaf(A5, y0, fmaf(A6, z0, A7))) * inv;
        out[3 * i0 + 2] = fmaf(A8, x0, fmaf(A9, y0, fmaf(A10, z0, A11))) * inv;
    }
    if (v1) {
        float inv;
        asm("rcp.approx.f32 %0, %1;" : "=f"(inv) : "f"(s1));
        float A0, A1, A2, A3, A4, A5, A6, A7, A8, A9, A10, A11;
        upk2(C01, A0, A1);  upk2(C23, A2, A3);
        upk2(C45, A4, A5);  upk2(C67, A6, A7);
        upk2(C89, A8, A9);  upk2(CAB, A10, A11);
        out[3 * i1 + 0] = fmaf(A0, x1, fmaf(A1, y1, fmaf(A2, z1, A3))) * inv;
        out[3 * i1 + 1] = fmaf(A4, x1, fmaf(A5, y1, fmaf(A6, z1, A7))) * inv;
        out[3 * i1 + 2] = fmaf(A8, x1, fmaf(A9, y1, fmaf(A10, z1, A11))) * inv;
    }
}

extern "C" void kernel_launch(void* const* d_in, const int* in_sizes, int n_in,
                              void* d_out, int out_size) {
    const float* xyz  = (const float*)d_in[0];   // [N, 3]
    const float* locs = (const float*)d_in[1];   // [512, 3]
    const float* bt   = (const float*)d_in[2];   // [64, 512, 9]
    const int*   tidx = (const int*)d_in[3];     // scalar

    int n = in_sizes[0] / 3;

    prep_kernel<<<(K_BONES + 255) / 256, 256>>>(locs, bt, tidx);
    int pts_per_block = 256 * 2;
    skin_kernel<<<(n + pts_per_block - 1) / pts_per_block, 256>>>(
        xyz, (float*)d_out, n);
}

// round 4
// speedup vs baseline: 1.0620x; 1.0620x over previous
#include <cuda_runtime.h>
#include <cuda_bf16.h>

#define K_BONES 512
#define SCALE 28.853900817779268f   // SIGMA * log2(e), SIGMA = 20

typedef unsigned long long u64;

// Per bone, 4 float4s (64 B):
//   [0] = (S*bx, S*by, S*bz, 0)      bone loc pre-scaled by S = sigma*log2(e)
//   [1] = (R00, R01, R02, t0)        row0 of [R|t]
//   [2] = (R10, R11, R12, t1)
//   [3] = (R20, R21, R22, t2)
__device__ float4 g_bones[K_BONES * 4];

// ---------------------------------------------------------------------------
// Precompute: 6D rotation -> rotmat (Gram-Schmidt) + pack. 512 threads total.
// rotcont reshape(3,2) row-major: a1=(p0,p2,p4), a2=(p1,p3,p5).
// rotmat columns are (b1,b2,b3) => row i = (b1[i], b2[i], b3[i]).
// ---------------------------------------------------------------------------
__global__ void prep_kernel(const float* __restrict__ bone_locs,
                            const float* __restrict__ bone_transf,
                            const int* __restrict__ tidx_p) {
    int k = blockIdx.x * blockDim.x + threadIdx.x;
    if (k >= K_BONES) return;
    const float* p = bone_transf + ((long long)tidx_p[0] * K_BONES + k) * 9;

    float a1x = p[0], a2x = p[1];
    float a1y = p[2], a2y = p[3];
    float a1z = p[4], a2z = p[5];

    float n1 = sqrtf(a1x * a1x + a1y * a1y + a1z * a1z) + 1e-12f;
    float b1x = a1x / n1, b1y = a1y / n1, b1z = a1z / n1;

    float d = b1x * a2x + b1y * a2y + b1z * a2z;
    float cx = a2x - d * b1x, cy = a2y - d * b1y, cz = a2z - d * b1z;
    float n2 = sqrtf(cx * cx + cy * cy + cz * cz) + 1e-12f;
    float b2x = cx / n2, b2y = cy / n2, b2z = cz / n2;

    float b3x = b1y * b2z - b1z * b2y;
    float b3y = b1z * b2x - b1x * b2z;
    float b3z = b1x * b2y - b1y * b2x;

    g_bones[4 * k + 0] = make_float4(SCALE * bone_locs[3 * k + 0],
                                     SCALE * bone_locs[3 * k + 1],
                                     SCALE * bone_locs[3 * k + 2], 0.0f);
    g_bones[4 * k + 1] = make_float4(b1x, b2x, b3x, p[6]);
    g_bones[4 * k + 2] = make_float4(b1y, b2y, b3y, p[7]);
    g_bones[4 * k + 3] = make_float4(b1z, b2z, b3z, p[8]);
}

// ---- packed f32x2 helpers (sm_100a) ---------------------------------------
__device__ __forceinline__ u64 pk2(float lo, float hi) {
    u64 r;
    asm("mov.b64 %0, {%1, %2};" : "=l"(r) : "f"(lo), "f"(hi));
    return r;
}
__device__ __forceinline__ void upk2(u64 v, float& lo, float& hi) {
    asm("mov.b64 {%0, %1}, %2;" : "=f"(lo), "=f"(hi) : "l"(v));
}
__device__ __forceinline__ u64 addx2(u64 a, u64 b) {
    u64 r;
    asm("add.rn.f32x2 %0, %1, %2;" : "=l"(r) : "l"(a), "l"(b));
    return r;
}
__device__ __forceinline__ u64 mulx2(u64 a, u64 b) {
    u64 r;
    asm("mul.rn.f32x2 %0, %1, %2;" : "=l"(r) : "l"(a), "l"(b));
    return r;
}
__device__ __forceinline__ u64 fmax2(u64 a, u64 b, u64 c) {
    u64 r;
    asm("fma.rn.f32x2 %0, %1, %2, %3;" : "=l"(r) : "l"(a), "l"(b), "l"(c));
    return r;
}

// ---------------------------------------------------------------------------
// Main kernel: 128-thread blocks, 2 points/thread (bone smem amortized over
// both), stage-interleaved so the two MUFU chains overlap. Coordinates
// pre-scaled by S so e = ex2(-sqrt(d2')) directly (no per-iter multiply).
// ---------------------------------------------------------------------------
__global__ __launch_bounds__(128)
void skin_kernel(const float* __restrict__ xyz,
                 float* __restrict__ out, int n) {
    __shared__ ulonglong2 sb[K_BONES * 4];   // 32 KB
    {
        const ulonglong2* gb = (const ulonglong2*)g_bones;
        for (int i = threadIdx.x; i < K_BONES * 4; i += 128)
            sb[i] = gb[i];
    }
    __syncthreads();

    int base = blockIdx.x * 256;
    int i0 = base + threadIdx.x;
    int i1 = i0 + 128;
    bool v0 = i0 < n, v1 = i1 < n;

    float x0 = 0.f, y0 = 0.f, z0 = 0.f, x1 = 0.f, y1 = 0.f, z1 = 0.f;
    if (v0) { x0 = xyz[3 * i0]; y0 = xyz[3 * i0 + 1]; z0 = xyz[3 * i0 + 2]; }
    if (v1) { x1 = xyz[3 * i1]; y1 = xyz[3 * i1 + 1]; z1 = xyz[3 * i1 + 2]; }

    // scaled negated coords for distance; raw coords kept for final apply
    u64 nxy0 = pk2(-SCALE * x0, -SCALE * y0);
    u64 nxy1 = pk2(-SCALE * x1, -SCALE * y1);
    float nz0 = -SCALE * z0, nz1 = -SCALE * z1;

    float s0 = 0.f, s1 = 0.f;
    u64 B01 = 0, B23 = 0, B45 = 0, B67 = 0, B89 = 0, BAB = 0;  // point0
    u64 C01 = 0, C23 = 0, C45 = 0, C67 = 0, C89 = 0, CAB = 0;  // point1

    const ulonglong2* p = sb;
    #pragma unroll 8
    for (int k = 0; k < K_BONES; k++, p += 4) {
        ulonglong2 qa = p[0];
        float bz, pad;  upk2(qa.y, bz, pad);

        // stage 1: both squared distances (scaled)
        u64 dA = addx2(qa.x, nxy0);
        u64 dB = addx2(qa.x, nxy1);
        float dzA = bz + nz0;
        float dzB = bz + nz1;
        u64 dA2 = mulx2(dA, dA);
        u64 dB2 = mulx2(dB, dB);
        float a0, a1;  upk2(dA2, a0, a1);
        float b0, b1;  upk2(dB2, b0, b1);
        float d2A = fmaf(dzA, dzA, a0) + a1;
        float d2B = fmaf(dzB, dzB, b0) + b1;

        // stage 2: both MUFU chains (overlapped)
        float distA, distB;
        asm("sqrt.approx.f32 %0, %1;" : "=f"(distA) : "f"(d2A));
        asm("sqrt.approx.f32 %0, %1;" : "=f"(distB) : "f"(d2B));
        float eA, eB;
        asm("ex2.approx.f32 %0, %1;" : "=f"(eA) : "f"(-distA));
        asm("ex2.approx.f32 %0, %1;" : "=f"(eB) : "f"(-distB));

        // stage 3: accumulate
        ulonglong2 qb = p[1];
        ulonglong2 qc = p[2];
        ulonglong2 qd = p[3];
        s0 += eA;
        s1 += eB;
        u64 eA2 = pk2(eA, eA);
        u64 eB2 = pk2(eB, eB);
        B01 = fmax2(eA2, qb.x, B01);  C01 = fmax2(eB2, qb.x, C01);
        B23 = fmax2(eA2, qb.y, B23);  C23 = fmax2(eB2, qb.y, C23);
        B45 = fmax2(eA2, qc.x, B45);  C45 = fmax2(eB2, qc.x, C45);
        B67 = fmax2(eA2, qc.y, B67);  C67 = fmax2(eB2, qc.y, C67);
        B89 = fmax2(eA2, qd.x, B89);  C89 = fmax2(eB2, qd.x, C89);
        BAB = fmax2(eA2, qd.y, BAB);  CAB = fmax2(eB2, qd.y, CAB);
    }

    if (v0) {
        float inv;
        asm("rcp.approx.f32 %0, %1;" : "=f"(inv) : "f"(s0));
        float A0, A1, A2, A3, A4, A5, A6, A7, A8, A9, A10, A11;
        upk2(B01, A0, A1);  upk2(B23, A2, A3);
        upk2(B45, A4, A5);  upk2(B67, A6, A7);
        upk2(B89, A8, A9);  upk2(BAB, A10, A11);
        out[3 * i0 + 0] = fmaf(A0, x0, fmaf(A1, y0, fmaf(A2, z0, A3))) * inv;
        out[3 * i0 + 1] = fmaf(A4, x0, fmaf(A5, y0, fmaf(A6, z0, A7))) * inv;
        out[3 * i0 + 2] = fmaf(A8, x0, fmaf(A9, y0, fmaf(A10, z0, A11))) * inv;
    }
    if (v1) {
        float inv;
        asm("rcp.approx.f32 %0, %1;" : "=f"(inv) : "f"(s1));
        float A0, A1, A2, A3, A4, A5, A6, A7, A8, A9, A10, A11;
        upk2(C01, A0, A1);  upk2(C23, A2, A3);
        upk2(C45, A4, A5);  upk2(C67, A6, A7);
        upk2(C89, A8, A9);  upk2(CAB, A10, A11);
        out[3 * i1 + 0] = fmaf(A0, x1, fmaf(A1, y1, fmaf(A2, z1, A3))) * inv;
        out[3 * i1 + 1] = fmaf(A4, x1, fmaf(A5, y1, fmaf(A6, z1, A7))) * inv;
        out[3 * i1 + 2] = fmaf(A8, x1, fmaf(A9, y1, fmaf(A10, z1, A11))) * inv;
    }
}

extern "C" void kernel_launch(void* const* d_in, const int* in_sizes, int n_in,
                              void* d_out, int out_size) {
    const float* xyz  = (const float*)d_in[0];   // [N, 3]
    const float* locs = (const float*)d_in[1];   // [512, 3]
    const float* bt   = (const float*)d_in[2];   // [64, 512, 9]
    const int*   tidx = (const int*)d_in[3];     // scalar

    int n = in_sizes[0] / 3;

    prep_kernel<<<(K_BONES + 255) / 256, 256>>>(locs, bt, tidx);
    int pts_per_block = 128 * 2;
    skin_kernel<<<(n + pts_per_block - 1) / pts_per_block, 128>>>(
        xyz, (float*)d_out, n);
}

// round 5
// speedup vs baseline: 1.1278x; 1.0620x over previous
#include <cuda_runtime.h>
#include <cuda_bf16.h>

#define K_BONES 512
#define SCALE 28.853900817779268f   // SIGMA * log2(e), SIGMA = 20

typedef unsigned long long u64;

// Per bone, 4 float4s (64 B):
//   [0] = (S*bx, S*by, S*bz, 0)      bone loc pre-scaled by S = sigma*log2(e)
//   [1] = (R00, R01, R02, t0)        row0 of [R|t]
//   [2] = (R10, R11, R12, t1)
//   [3] = (R20, R21, R22, t2)
__device__ float4 g_bones[K_BONES * 4];

// ---------------------------------------------------------------------------
// Precompute: 6D rotation -> rotmat (Gram-Schmidt) + pack. 512 threads total.
// rotcont reshape(3,2) row-major: a1=(p0,p2,p4), a2=(p1,p3,p5).
// rotmat columns are (b1,b2,b3) => row i = (b1[i], b2[i], b3[i]).
// ---------------------------------------------------------------------------
__global__ void prep_kernel(const float* __restrict__ bone_locs,
                            const float* __restrict__ bone_transf,
                            const int* __restrict__ tidx_p) {
    int k = blockIdx.x * blockDim.x + threadIdx.x;
    if (k >= K_BONES) return;
    const float* p = bone_transf + ((long long)tidx_p[0] * K_BONES + k) * 9;

    float a1x = p[0], a2x = p[1];
    float a1y = p[2], a2y = p[3];
    float a1z = p[4], a2z = p[5];

    float n1 = sqrtf(a1x * a1x + a1y * a1y + a1z * a1z) + 1e-12f;
    float b1x = a1x / n1, b1y = a1y / n1, b1z = a1z / n1;

    float d = b1x * a2x + b1y * a2y + b1z * a2z;
    float cx = a2x - d * b1x, cy = a2y - d * b1y, cz = a2z - d * b1z;
    float n2 = sqrtf(cx * cx + cy * cy + cz * cz) + 1e-12f;
    float b2x = cx / n2, b2y = cy / n2, b2z = cz / n2;

    float b3x = b1y * b2z - b1z * b2y;
    float b3y = b1z * b2x - b1x * b2z;
    float b3z = b1x * b2y - b1y * b2x;

    g_bones[4 * k + 0] = make_float4(SCALE * bone_locs[3 * k + 0],
                                     SCALE * bone_locs[3 * k + 1],
                                     SCALE * bone_locs[3 * k + 2], 0.0f);
    g_bones[4 * k + 1] = make_float4(b1x, b2x, b3x, p[6]);
    g_bones[4 * k + 2] = make_float4(b1y, b2y, b3y, p[7]);
    g_bones[4 * k + 3] = make_float4(b1z, b2z, b3z, p[8]);
}

// ---- packed f32x2 helpers (sm_100a) ---------------------------------------
__device__ __forceinline__ u64 pk2(float lo, float hi) {
    u64 r;
    asm("mov.b64 %0, {%1, %2};" : "=l"(r) : "f"(lo), "f"(hi));
    return r;
}
__device__ __forceinline__ void upk2(u64 v, float& lo, float& hi) {
    asm("mov.b64 {%0, %1}, %2;" : "=f"(lo), "=f"(hi) : "l"(v));
}
__device__ __forceinline__ u64 addx2(u64 a, u64 b) {
    u64 r;
    asm("add.rn.f32x2 %0, %1, %2;" : "=l"(r) : "l"(a), "l"(b));
    return r;
}
__device__ __forceinline__ u64 mulx2(u64 a, u64 b) {
    u64 r;
    asm("mul.rn.f32x2 %0, %1, %2;" : "=l"(r) : "l"(a), "l"(b));
    return r;
}
__device__ __forceinline__ u64 fmax2(u64 a, u64 b, u64 c) {
    u64 r;
    asm("fma.rn.f32x2 %0, %1, %2, %3;" : "=l"(r) : "l"(a), "l"(b), "l"(c));
    return r;
}

// ---------------------------------------------------------------------------
// Main kernel: 128-thread blocks, 2 points/thread. Distance math packed over
// the POINT pair (bone coords duplicated into both lanes via ALU movs —
// shifts work from the saturated fma pipe to the idle alu pipe):
//   d2(A,B) = (b-pA, b-pB) squared, 6 fma-pipe ops total.
// Blend stays packed over matrix columns (data natural from LDS.128 lanes).
// One-pass no-max softmax, coords pre-scaled so e = ex2(-sqrt(d2')).
// ---------------------------------------------------------------------------
__global__ __launch_bounds__(128)
void skin_kernel(const float* __restrict__ xyz,
                 float* __restrict__ out, int n) {
    __shared__ ulonglong2 sb[K_BONES * 4];   // 32 KB
    {
        const ulonglong2* gb = (const ulonglong2*)g_bones;
        for (int i = threadIdx.x; i < K_BONES * 4; i += 128)
            sb[i] = gb[i];
    }
    __syncthreads();

    int base = blockIdx.x * 256;
    int i0 = base + threadIdx.x;
    int i1 = i0 + 128;
    bool v0 = i0 < n, v1 = i1 < n;

    float x0 = 0.f, y0 = 0.f, z0 = 0.f, x1 = 0.f, y1 = 0.f, z1 = 0.f;
    if (v0) { x0 = xyz[3 * i0]; y0 = xyz[3 * i0 + 1]; z0 = xyz[3 * i0 + 2]; }
    if (v1) { x1 = xyz[3 * i1]; y1 = xyz[3 * i1 + 1]; z1 = xyz[3 * i1 + 2]; }

    // negated scaled coords, packed over the point pair
    u64 nx01 = pk2(-SCALE * x0, -SCALE * x1);
    u64 ny01 = pk2(-SCALE * y0, -SCALE * y1);
    u64 nz01 = pk2(-SCALE * z0, -SCALE * z1);

    u64 s01 = 0;                                               // (s0, s1)
    u64 B01 = 0, B23 = 0, B45 = 0, B67 = 0, B89 = 0, BAB = 0;  // point0
    u64 C01 = 0, C23 = 0, C45 = 0, C67 = 0, C89 = 0, CAB = 0;  // point1

    const ulonglong2* p = sb;
    #pragma unroll 4
    for (int k = 0; k < K_BONES; k++, p += 4) {
        ulonglong2 qa = p[0];            // (Sbx,Sby) | (Sbz, 0)
        float bx, by, bz, pad;
        upk2(qa.x, bx, by);
        upk2(qa.y, bz, pad);
        u64 bxx = pk2(bx, bx);           // ALU movs (fma pipe untouched)
        u64 byy = pk2(by, by);
        u64 bzz = pk2(bz, bz);

        // packed distance: lane0 = point0, lane1 = point1
        u64 dx = addx2(bxx, nx01);
        u64 dy = addx2(byy, ny01);
        u64 dz = addx2(bzz, nz01);
        u64 d2 = mulx2(dx, dx);
        d2 = fmax2(dy, dy, d2);
        d2 = fmax2(dz, dz, d2);
        float d2A, d2B;  upk2(d2, d2A, d2B);

        float distA, distB;
        asm("sqrt.approx.f32 %0, %1;" : "=f"(distA) : "f"(d2A));
        asm("sqrt.approx.f32 %0, %1;" : "=f"(distB) : "f"(d2B));
        float eA, eB;
        asm("ex2.approx.f32 %0, %1;" : "=f"(eA) : "f"(-distA));
        asm("ex2.approx.f32 %0, %1;" : "=f"(eB) : "f"(-distB));

        s01 = addx2(s01, pk2(eA, eB));
        u64 eA2 = pk2(eA, eA);
        u64 eB2 = pk2(eB, eB);

        ulonglong2 qb = p[1];
        ulonglong2 qc = p[2];
        ulonglong2 qd = p[3];
        B01 = fmax2(eA2, qb.x, B01);  C01 = fmax2(eB2, qb.x, C01);
        B23 = fmax2(eA2, qb.y, B23);  C23 = fmax2(eB2, qb.y, C23);
        B45 = fmax2(eA2, qc.x, B45);  C45 = fmax2(eB2, qc.x, C45);
        B67 = fmax2(eA2, qc.y, B67);  C67 = fmax2(eB2, qc.y, C67);
        B89 = fmax2(eA2, qd.x, B89);  C89 = fmax2(eB2, qd.x, C89);
        BAB = fmax2(eA2, qd.y, BAB);  CAB = fmax2(eB2, qd.y, CAB);
    }

    float s0, s1;  upk2(s01, s0, s1);

    if (v0) {
        float inv;
        asm("rcp.approx.f32 %0, %1;" : "=f"(inv) : "f"(s0));
        float A0, A1, A2, A3, A4, A5, A6, A7, A8, A9, A10, A11;
        upk2(B01, A0, A1);  upk2(B23, A2, A3);
        upk2(B45, A4, A5);  upk2(B67, A6, A7);
        upk2(B89, A8, A9);  upk2(BAB, A10, A11);
        out[3 * i0 + 0] = fmaf(A0, x0, fmaf(A1, y0, fmaf(A2, z0, A3))) * inv;
        out[3 * i0 + 1] = fmaf(A4, x0, fmaf(A5, y0, fmaf(A6, z0, A7))) * inv;
        out[3 * i0 + 2] = fmaf(A8, x0, fmaf(A9, y0, fmaf(A10, z0, A11))) * inv;
    }
    if (v1) {
        float inv;
        asm("rcp.approx.f32 %0, %1;" : "=f"(inv) : "f"(s1));
        float A0, A1, A2, A3, A4, A5, A6, A7, A8, A9, A10, A11;
        upk2(C01, A0, A1);  upk2(C23, A2, A3);
        upk2(C45, A4, A5);  upk2(C67, A6, A7);
        upk2(C89, A8, A9);  upk2(CAB, A10, A11);
        out[3 * i1 + 0] = fmaf(A0, x1, fmaf(A1, y1, fmaf(A2, z1, A3))) * inv;
        out[3 * i1 + 1] = fmaf(A4, x1, fmaf(A5, y1, fmaf(A6, z1, A7))) * inv;
        out[3 * i1 + 2] = fmaf(A8, x1, fmaf(A9, y1, fmaf(A10, z1, A11))) * inv;
    }
}

extern "C" void kernel_launch(void* const* d_in, const int* in_sizes, int n_in,
                              void* d_out, int out_size) {
    const float* xyz  = (const float*)d_in[0];   // [N, 3]
    const float* locs = (const float*)d_in[1];   // [512, 3]
    const float* bt   = (const float*)d_in[2];   // [64, 512, 9]
    const int*   tidx = (const int*)d_in[3];     // scalar

    int n = in_sizes[0] / 3;

    prep_kernel<<<(K_BONES + 255) / 256, 256>>>(locs, bt, tidx);
    int pts_per_block = 128 * 2;
    skin_kernel<<<(n + pts_per_block - 1) / pts_per_block, 128>>>(
        xyz, (float*)d_out, n);
}

// round 6
// speedup vs baseline: 1.2076x; 1.0708x over previous
#include <cuda_runtime.h>
#include <cuda_bf16.h>

#define K_BONES 512
#define K_SPLIT 2
#define K_HALF (K_BONES / K_SPLIT)
#define MAXN 200192
#define SCALE 28.853900817779268f   // SIGMA * log2(e), SIGMA = 20

typedef unsigned long long u64;

// Per bone, 4 float4s (64 B):
//   [0] = (S*bx, S*by, S*bz, 0)
//   [1] = (R00, R01, R02, t0)   row0 of [R|t]
//   [2] = (R10, R11, R12, t1)
//   [3] = (R20, R21, R22, t2)
__device__ float4 g_bones[K_BONES * 4];

// Partial results per (half, point): 3 float4 of blend accum + scalar s.
__device__ float4 g_acc[K_SPLIT * MAXN * 3];
__device__ float  g_s[K_SPLIT * MAXN];

// ---------------------------------------------------------------------------
// Precompute: 6D rotation -> rotmat (Gram-Schmidt) + pack. 512 threads total.
// ---------------------------------------------------------------------------
__global__ void prep_kernel(const float* __restrict__ bone_locs,
                            const float* __restrict__ bone_transf,
                            const int* __restrict__ tidx_p) {
    int k = blockIdx.x * blockDim.x + threadIdx.x;
    if (k >= K_BONES) return;
    const float* p = bone_transf + ((long long)tidx_p[0] * K_BONES + k) * 9;

    float a1x = p[0], a2x = p[1];
    float a1y = p[2], a2y = p[3];
    float a1z = p[4], a2z = p[5];

    float n1 = sqrtf(a1x * a1x + a1y * a1y + a1z * a1z) + 1e-12f;
    float b1x = a1x / n1, b1y = a1y / n1, b1z = a1z / n1;

    float d = b1x * a2x + b1y * a2y + b1z * a2z;
    float cx = a2x - d * b1x, cy = a2y - d * b1y, cz = a2z - d * b1z;
    float n2 = sqrtf(cx * cx + cy * cy + cz * cz) + 1e-12f;
    float b2x = cx / n2, b2y = cy / n2, b2z = cz / n2;

    float b3x = b1y * b2z - b1z * b2y;
    float b3y = b1z * b2x - b1x * b2z;
    float b3z = b1x * b2y - b1y * b2x;

    g_bones[4 * k + 0] = make_float4(SCALE * bone_locs[3 * k + 0],
                                     SCALE * bone_locs[3 * k + 1],
                                     SCALE * bone_locs[3 * k + 2], 0.0f);
    g_bones[4 * k + 1] = make_float4(b1x, b2x, b3x, p[6]);
    g_bones[4 * k + 2] = make_float4(b1y, b2y, b3y, p[7]);
    g_bones[4 * k + 3] = make_float4(b1z, b2z, b3z, p[8]);
}

// ---- packed f32x2 helpers (sm_100a) ---------------------------------------
__device__ __forceinline__ u64 pk2(float lo, float hi) {
    u64 r;
    asm("mov.b64 %0, {%1, %2};" : "=l"(r) : "f"(lo), "f"(hi));
    return r;
}
__device__ __forceinline__ void upk2(u64 v, float& lo, float& hi) {
    asm("mov.b64 {%0, %1}, %2;" : "=f"(lo), "=f"(hi) : "l"(v));
}
__device__ __forceinline__ u64 addx2(u64 a, u64 b) {
    u64 r;
    asm("add.rn.f32x2 %0, %1, %2;" : "=l"(r) : "l"(a), "l"(b));
    return r;
}
__device__ __forceinline__ u64 mulx2(u64 a, u64 b) {
    u64 r;
    asm("mul.rn.f32x2 %0, %1, %2;" : "=l"(r) : "l"(a), "l"(b));
    return r;
}
__device__ __forceinline__ u64 fmax2(u64 a, u64 b, u64 c) {
    u64 r;
    asm("fma.rn.f32x2 %0, %1, %2, %3;" : "=l"(r) : "l"(a), "l"(b), "l"(c));
    return r;
}

// ---------------------------------------------------------------------------
// Partial kernel: blockIdx.y selects a half of the bones (256 bones, 16 KB
// smem). 128 threads, 2 points/thread, point-pair-packed distance math.
// Writes 12-float blend partial + partial softmax denominator to scratch.
// __launch_bounds__(128, 8): cap 64 regs -> 8 blocks = 32 warps/SM.
// ---------------------------------------------------------------------------
__global__ __launch_bounds__(128, 8)
void skin_partial_kernel(const float* __restrict__ xyz, int n) {
    __shared__ ulonglong2 sb[K_HALF * 4];   // 16 KB
    {
        const ulonglong2* gb =
            (const ulonglong2*)g_bones + (size_t)blockIdx.y * (K_HALF * 4);
        for (int i = threadIdx.x; i < K_HALF * 4; i += 128)
            sb[i] = gb[i];
    }
    __syncthreads();

    int base = blockIdx.x * 256;
    int i0 = base + threadIdx.x;
    int i1 = i0 + 128;
    bool v0 = i0 < n, v1 = i1 < n;

    float x0 = 0.f, y0 = 0.f, z0 = 0.f, x1 = 0.f, y1 = 0.f, z1 = 0.f;
    if (v0) { x0 = xyz[3 * i0]; y0 = xyz[3 * i0 + 1]; z0 = xyz[3 * i0 + 2]; }
    if (v1) { x1 = xyz[3 * i1]; y1 = xyz[3 * i1 + 1]; z1 = xyz[3 * i1 + 2]; }

    u64 nx01 = pk2(-SCALE * x0, -SCALE * x1);
    u64 ny01 = pk2(-SCALE * y0, -SCALE * y1);
    u64 nz01 = pk2(-SCALE * z0, -SCALE * z1);

    u64 s01 = 0;
    u64 B01 = 0, B23 = 0, B45 = 0, B67 = 0, B89 = 0, BAB = 0;  // point0
    u64 C01 = 0, C23 = 0, C45 = 0, C67 = 0, C89 = 0, CAB = 0;  // point1

    const ulonglong2* p = sb;
    #pragma unroll 2
    for (int k = 0; k < K_HALF; k++, p += 4) {
        ulonglong2 qa = p[0];
        float bx, by, bz, pad;
        upk2(qa.x, bx, by);
        upk2(qa.y, bz, pad);
        u64 bxx = pk2(bx, bx);
        u64 byy = pk2(by, by);
        u64 bzz = pk2(bz, bz);

        u64 dx = addx2(bxx, nx01);
        u64 dy = addx2(byy, ny01);
        u64 dz = addx2(bzz, nz01);
        u64 d2 = mulx2(dx, dx);
        d2 = fmax2(dy, dy, d2);
        d2 = fmax2(dz, dz, d2);
        float d2A, d2B;  upk2(d2, d2A, d2B);

        float distA, distB;
        asm("sqrt.approx.f32 %0, %1;" : "=f"(distA) : "f"(d2A));
        asm("sqrt.approx.f32 %0, %1;" : "=f"(distB) : "f"(d2B));
        float eA, eB;
        asm("ex2.approx.f32 %0, %1;" : "=f"(eA) : "f"(-distA));
        asm("ex2.approx.f32 %0, %1;" : "=f"(eB) : "f"(-distB));

        s01 = addx2(s01, pk2(eA, eB));
        u64 eA2 = pk2(eA, eA);
        u64 eB2 = pk2(eB, eB);

        ulonglong2 qb = p[1];
        ulonglong2 qc = p[2];
        ulonglong2 qd = p[3];
        B01 = fmax2(eA2, qb.x, B01);  C01 = fmax2(eB2, qb.x, C01);
        B23 = fmax2(eA2, qb.y, B23);  C23 = fmax2(eB2, qb.y, C23);
        B45 = fmax2(eA2, qc.x, B45);  C45 = fmax2(eB2, qc.x, C45);
        B67 = fmax2(eA2, qc.y, B67);  C67 = fmax2(eB2, qc.y, C67);
        B89 = fmax2(eA2, qd.x, B89);  C89 = fmax2(eB2, qd.x, C89);
        BAB = fmax2(eA2, qd.y, BAB);  CAB = fmax2(eB2, qd.y, CAB);
    }

    float s0, s1;  upk2(s01, s0, s1);
    size_t hb = (size_t)blockIdx.y * MAXN;

    if (v0) {
        float A0, A1, A2, A3, A4, A5, A6, A7, A8, A9, A10, A11;
        upk2(B01, A0, A1);  upk2(B23, A2, A3);
        upk2(B45, A4, A5);  upk2(B67, A6, A7);
        upk2(B89, A8, A9);  upk2(BAB, A10, A11);
        g_acc[(hb + i0) * 3 + 0] = make_float4(A0, A1, A2, A3);
        g_acc[(hb + i0) * 3 + 1] = make_float4(A4, A5, A6, A7);
        g_acc[(hb + i0) * 3 + 2] = make_float4(A8, A9, A10, A11);
        g_s[hb + i0] = s0;
    }
    if (v1) {
        float A0, A1, A2, A3, A4, A5, A6, A7, A8, A9, A10, A11;
        upk2(C01, A0, A1);  upk2(C23, A2, A3);
        upk2(C45, A4, A5);  upk2(C67, A6, A7);
        upk2(C89, A8, A9);  upk2(CAB, A10, A11);
        g_acc[(hb + i1) * 3 + 0] = make_float4(A0, A1, A2, A3);
        g_acc[(hb + i1) * 3 + 1] = make_float4(A4, A5, A6, A7);
        g_acc[(hb + i1) * 3 + 2] = make_float4(A8, A9, A10, A11);
        g_s[hb + i1] = s1;
    }
}

// ---------------------------------------------------------------------------
// Finalize: merge the two halves (exact partial-softmax combine), apply the
// blended transform, write output. Memory-bound, ~21 MB traffic.
// ---------------------------------------------------------------------------
__global__ __launch_bounds__(256)
void finalize_kernel(const float* __restrict__ xyz,
                     float* __restrict__ out, int n) {
    int i = blockIdx.x * blockDim.x + threadIdx.x;
    if (i >= n) return;

    float4 r0 = g_acc[(size_t)i * 3 + 0];
    float4 r1 = g_acc[(size_t)i * 3 + 1];
    float4 r2 = g_acc[(size_t)i * 3 + 2];
    float4 q0 = g_acc[((size_t)MAXN + i) * 3 + 0];
    float4 q1 = g_acc[((size_t)MAXN + i) * 3 + 1];
    float4 q2 = g_acc[((size_t)MAXN + i) * 3 + 2];
    float s = g_s[i] + g_s[MAXN + i];

    float x = xyz[3 * i], y = xyz[3 * i + 1], z = xyz[3 * i + 2];
    float inv;
    asm("rcp.approx.f32 %0, %1;" : "=f"(inv) : "f"(s));

    float A0 = r0.x + q0.x, A1 = r0.y + q0.y, A2 = r0.z + q0.z, A3 = r0.w + q0.w;
    float A4 = r1.x + q1.x, A5 = r1.y + q1.y, A6 = r1.z + q1.z, A7 = r1.w + q1.w;
    float A8 = r2.x + q2.x, A9 = r2.y + q2.y, A10 = r2.z + q2.z, A11 = r2.w + q2.w;

    out[3 * i + 0] = fmaf(A0, x, fmaf(A1, y, fmaf(A2, z, A3))) * inv;
    out[3 * i + 1] = fmaf(A4, x, fmaf(A5, y, fmaf(A6, z, A7))) * inv;
    out[3 * i + 2] = fmaf(A8, x, fmaf(A9, y, fmaf(A10, z, A11))) * inv;
}

extern "C" void kernel_launch(void* const* d_in, const int* in_sizes, int n_in,
                              void* d_out, int out_size) {
    const float* xyz  = (const float*)d_in[0];   // [N, 3]
    const float* locs = (const float*)d_in[1];   // [512, 3]
    const float* bt   = (const float*)d_in[2];   // [64, 512, 9]
    const int*   tidx = (const int*)d_in[3];     // scalar

    int n = in_sizes[0] / 3;

    prep_kernel<<<(K_BONES + 255) / 256, 256>>>(locs, bt, tidx);

    dim3 grid((n + 255) / 256, K_SPLIT);
    skin_partial_kernel<<<grid, 128>>>(xyz, n);

    finalize_kernel<<<(n + 255) / 256, 256>>>(xyz, (float*)d_out, n);
}

// round 7
// speedup vs baseline: 1.2126x; 1.0041x over previous
#include <cuda_runtime.h>
#include <cuda_bf16.h>

#define K_BONES 512
#define K_SPLIT 2
#define K_HALF (K_BONES / K_SPLIT)
#define MAXN 200192
#define SCALE 28.853900817779268f   // SIGMA * log2(e), SIGMA = 20

typedef unsigned long long u64;

// Partial results per (half, point): 3 float4 of blend accum + scalar s.
__device__ float4 g_acc[K_SPLIT * MAXN * 3];
__device__ float  g_s[K_SPLIT * MAXN];

// ---- packed f32x2 helpers (sm_100a) ---------------------------------------
__device__ __forceinline__ u64 pk2(float lo, float hi) {
    u64 r;
    asm("mov.b64 %0, {%1, %2};" : "=l"(r) : "f"(lo), "f"(hi));
    return r;
}
__device__ __forceinline__ void upk2(u64 v, float& lo, float& hi) {
    asm("mov.b64 {%0, %1}, %2;" : "=f"(lo), "=f"(hi) : "l"(v));
}
__device__ __forceinline__ u64 addx2(u64 a, u64 b) {
    u64 r;
    asm("add.rn.f32x2 %0, %1, %2;" : "=l"(r) : "l"(a), "l"(b));
    return r;
}
__device__ __forceinline__ u64 mulx2(u64 a, u64 b) {
    u64 r;
    asm("mul.rn.f32x2 %0, %1, %2;" : "=l"(r) : "l"(a), "l"(b));
    return r;
}
__device__ __forceinline__ u64 fmax2(u64 a, u64 b, u64 c) {
    u64 r;
    asm("fma.rn.f32x2 %0, %1, %2, %3;" : "=l"(r) : "l"(a), "l"(b), "l"(c));
    return r;
}

// Point-pair-packed weight: e = ex2(-sqrt(d2)) for both points (coords are
// pre-scaled by S = sigma*log2(e)).
__device__ __forceinline__ void bone_e(ulonglong2 qa, u64 nx01, u64 ny01,
                                       u64 nz01, float& eA, float& eB) {
    float bx, by, bz, pad;
    upk2(qa.x, bx, by);
    upk2(qa.y, bz, pad);
    u64 dx = addx2(pk2(bx, bx), nx01);
    u64 dy = addx2(pk2(by, by), ny01);
    u64 dz = addx2(pk2(bz, bz), nz01);
    u64 d2 = mulx2(dx, dx);
    d2 = fmax2(dy, dy, d2);
    d2 = fmax2(dz, dz, d2);
    float d2A, d2B;  upk2(d2, d2A, d2B);
    float distA, distB;
    asm("sqrt.approx.f32 %0, %1;" : "=f"(distA) : "f"(d2A));
    asm("sqrt.approx.f32 %0, %1;" : "=f"(distB) : "f"(d2B));
    asm("ex2.approx.f32 %0, %1;" : "=f"(eA) : "f"(-distA));
    asm("ex2.approx.f32 %0, %1;" : "=f"(eB) : "f"(-distB));
}

// ---------------------------------------------------------------------------
// Partial kernel with INLINE bone prep (no separate prep launch): each block
// Gram-Schmidts its half's 256 bones into smem (source is 30 KB, L2-hot).
// Inner loop is software-pipelined: bone k+1's distance/sqrt/ex2 issues
// before bone k's 12-FMA blend, hiding the MUFU chain under the blend.
// 128 threads, 2 points/thread, __launch_bounds__(128, 8) -> 32 warps/SM.
// ---------------------------------------------------------------------------
__global__ __launch_bounds__(128, 8)
void skin_partial_kernel(const float* __restrict__ xyz,
                         const float* __restrict__ bone_locs,
                         const float* __restrict__ bone_transf,
                         const int* __restrict__ tidx_p, int n) {
    __shared__ ulonglong2 sb[K_HALF * 4];   // 16 KB
    {
        int t = tidx_p[0];
        for (int kk = threadIdx.x; kk < K_HALF; kk += 128) {
            int k = blockIdx.y * K_HALF + kk;
            const float* p = bone_transf + ((long long)t * K_BONES + k) * 9;

            float a1x = p[0], a2x = p[1];
            float a1y = p[2], a2y = p[3];
            float a1z = p[4], a2z = p[5];

            float n1 = sqrtf(a1x * a1x + a1y * a1y + a1z * a1z) + 1e-12f;
            float b1x = a1x / n1, b1y = a1y / n1, b1z = a1z / n1;

            float d = b1x * a2x + b1y * a2y + b1z * a2z;
            float cx = a2x - d * b1x, cy = a2y - d * b1y, cz = a2z - d * b1z;
            float n2 = sqrtf(cx * cx + cy * cy + cz * cz) + 1e-12f;
            float b2x = cx / n2, b2y = cy / n2, b2z = cz / n2;

            float b3x = b1y * b2z - b1z * b2y;
            float b3y = b1z * b2x - b1x * b2z;
            float b3z = b1x * b2y - b1y * b2x;

            float4* dst = (float4*)&sb[4 * kk];
            dst[0] = make_float4(SCALE * bone_locs[3 * k + 0],
                                 SCALE * bone_locs[3 * k + 1],
                                 SCALE * bone_locs[3 * k + 2], 0.0f);
            dst[1] = make_float4(b1x, b2x, b3x, p[6]);
            dst[2] = make_float4(b1y, b2y, b3y, p[7]);
            dst[3] = make_float4(b1z, b2z, b3z, p[8]);
        }
    }
    __syncthreads();

    int base = blockIdx.x * 256;
    int i0 = base + threadIdx.x;
    int i1 = i0 + 128;
    bool v0 = i0 < n, v1 = i1 < n;

    float x0 = 0.f, y0 = 0.f, z0 = 0.f, x1 = 0.f, y1 = 0.f, z1 = 0.f;
    if (v0) { x0 = xyz[3 * i0]; y0 = xyz[3 * i0 + 1]; z0 = xyz[3 * i0 + 2]; }
    if (v1) { x1 = xyz[3 * i1]; y1 = xyz[3 * i1 + 1]; z1 = xyz[3 * i1 + 2]; }

    u64 nx01 = pk2(-SCALE * x0, -SCALE * x1);
    u64 ny01 = pk2(-SCALE * y0, -SCALE * y1);
    u64 nz01 = pk2(-SCALE * z0, -SCALE * z1);

    u64 s01 = 0;
    u64 B01 = 0, B23 = 0, B45 = 0, B67 = 0, B89 = 0, BAB = 0;  // point0
    u64 C01 = 0, C23 = 0, C45 = 0, C67 = 0, C89 = 0, CAB = 0;  // point1

    const ulonglong2* p = sb;
    float eA, eB;
    bone_e(p[0], nx01, ny01, nz01, eA, eB);   // prologue: bone 0's weight

    #pragma unroll 2
    for (int k = 0; k < K_HALF - 1; k++, p += 4) {
        // issue next bone's distance + MUFU chain first (independent)
        float neA, neB;
        bone_e(p[4], nx01, ny01, nz01, neA, neB);

        // blend current bone under the in-flight MUFU chain
        s01 = addx2(s01, pk2(eA, eB));
        u64 eA2 = pk2(eA, eA);
        u64 eB2 = pk2(eB, eB);
        ulonglong2 qb = p[1];
        ulonglong2 qc = p[2];
        ulonglong2 qd = p[3];
        B01 = fmax2(eA2, qb.x, B01);  C01 = fmax2(eB2, qb.x, C01);
        B23 = fmax2(eA2, qb.y, B23);  C23 = fmax2(eB2, qb.y, C23);
        B45 = fmax2(eA2, qc.x, B45);  C45 = fmax2(eB2, qc.x, C45);
        B67 = fmax2(eA2, qc.y, B67);  C67 = fmax2(eB2, qc.y, C67);
        B89 = fmax2(eA2, qd.x, B89);  C89 = fmax2(eB2, qd.x, C89);
        BAB = fmax2(eA2, qd.y, BAB);  CAB = fmax2(eB2, qd.y, CAB);

        eA = neA;  eB = neB;
    }
    {   // epilogue: blend last bone
        s01 = addx2(s01, pk2(eA, eB));
        u64 eA2 = pk2(eA, eA);
        u64 eB2 = pk2(eB, eB);
        ulonglong2 qb = p[1];
        ulonglong2 qc = p[2];
        ulonglong2 qd = p[3];
        B01 = fmax2(eA2, qb.x, B01);  C01 = fmax2(eB2, qb.x, C01);
        B23 = fmax2(eA2, qb.y, B23);  C23 = fmax2(eB2, qb.y, C23);
        B45 = fmax2(eA2, qc.x, B45);  C45 = fmax2(eB2, qc.x, C45);
        B67 = fmax2(eA2, qc.y, B67);  C67 = fmax2(eB2, qc.y, C67);
        B89 = fmax2(eA2, qd.x, B89);  C89 = fmax2(eB2, qd.x, C89);
        BAB = fmax2(eA2, qd.y, BAB);  CAB = fmax2(eB2, qd.y, CAB);
    }

    float s0, s1;  upk2(s01, s0, s1);
    size_t hb = (size_t)blockIdx.y * MAXN;

    if (v0) {
        float A0, A1, A2, A3, A4, A5, A6, A7, A8, A9, A10, A11;
        upk2(B01, A0, A1);  upk2(B23, A2, A3);
        upk2(B45, A4, A5);  upk2(B67, A6, A7);
        upk2(B89, A8, A9);  upk2(BAB, A10, A11);
        g_acc[(hb + i0) * 3 + 0] = make_float4(A0, A1, A2, A3);
        g_acc[(hb + i0) * 3 + 1] = make_float4(A4, A5, A6, A7);
        g_acc[(hb + i0) * 3 + 2] = make_float4(A8, A9, A10, A11);
        g_s[hb + i0] = s0;
    }
    if (v1) {
        float A0, A1, A2, A3, A4, A5, A6, A7, A8, A9, A10, A11;
        upk2(C01, A0, A1);  upk2(C23, A2, A3);
        upk2(C45, A4, A5);  upk2(C67, A6, A7);
        upk2(C89, A8, A9);  upk2(CAB, A10, A11);
        g_acc[(hb + i1) * 3 + 0] = make_float4(A0, A1, A2, A3);
        g_acc[(hb + i1) * 3 + 1] = make_float4(A4, A5, A6, A7);
        g_acc[(hb + i1) * 3 + 2] = make_float4(A8, A9, A10, A11);
        g_s[hb + i1] = s1;
    }
}

// ---------------------------------------------------------------------------
// Finalize: merge the two halves (exact partial-softmax combine), apply the
// blended transform, write output. Memory-bound, ~21 MB traffic.
// ---------------------------------------------------------------------------
__global__ __launch_bounds__(256)
void finalize_kernel(const float* __restrict__ xyz,
                     float* __restrict__ out, int n) {
    int i = blockIdx.x * blockDim.x + threadIdx.x;
    if (i >= n) return;

    float4 r0 = g_acc[(size_t)i * 3 + 0];
    float4 r1 = g_acc[(size_t)i * 3 + 1];
    float4 r2 = g_acc[(size_t)i * 3 + 2];
    float4 q0 = g_acc[((size_t)MAXN + i) * 3 + 0];
    float4 q1 = g_acc[((size_t)MAXN + i) * 3 + 1];
    float4 q2 = g_acc[((size_t)MAXN + i) * 3 + 2];
    float s = g_s[i] + g_s[MAXN + i];

    float x = xyz[3 * i], y = xyz[3 * i + 1], z = xyz[3 * i + 2];
    float inv;
    asm("rcp.approx.f32 %0, %1;" : "=f"(inv) : "f"(s));

    float A0 = r0.x + q0.x, A1 = r0.y + q0.y, A2 = r0.z + q0.z, A3 = r0.w + q0.w;
    float A4 = r1.x + q1.x, A5 = r1.y + q1.y, A6 = r1.z + q1.z, A7 = r1.w + q1.w;
    float A8 = r2.x + q2.x, A9 = r2.y + q2.y, A10 = r2.z + q2.z, A11 = r2.w + q2.w;

    out[3 * i + 0] = fmaf(A0, x, fmaf(A1, y, fmaf(A2, z, A3))) * inv;
    out[3 * i + 1] = fmaf(A4, x, fmaf(A5, y, fmaf(A6, z, A7))) * inv;
    out[3 * i + 2] = fmaf(A8, x, fmaf(A9, y, fmaf(A10, z, A11))) * inv;
}

extern "C" void kernel_launch(void* const* d_in, const int* in_sizes, int n_in,
                              void* d_out, int out_size) {
    const float* xyz  = (const float*)d_in[0];   // [N, 3]
    const float* locs = (const float*)d_in[1];   // [512, 3]
    const float* bt   = (const float*)d_in[2];   // [64, 512, 9]
    const int*   tidx = (const int*)d_in[3];     // scalar

    int n = in_sizes[0] / 3;

    dim3 grid((n + 255) / 256, K_SPLIT);
    skin_partial_kernel<<<grid, 128>>>(xyz, locs, bt, tidx, n);

    finalize_kernel<<<(n + 255) / 256, 256>>>(xyz, (float*)d_out, n);
}